// round 15
// baseline (speedup 1.0000x reference)
#include <cuda_runtime.h>
#include <cuda_fp16.h>
#include <cstdint>
#include <cstddef>

// Problem constants
#define NN 32768
#define CCH 384
#define EE 384
#define GG 12
#define DD 32
#define PPAIR 16
#define NGRAPH 64
#define NQV 768

#define SW64(off) ((off) ^ (((off) >> 3) & 0x30))

// ---------------------------------------------------------------------------
// Scratch (q/k/v now fp16)
// ---------------------------------------------------------------------------
#define KVSPLIT 4
__device__ __half g_qh[(size_t)NN * EE];
__device__ __half g_vh[(size_t)NN * EE];
__device__ __half g_kh[(size_t)NN * EE];
__device__ float g_kv[(size_t)KVSPLIT * NGRAPH * GG * DD * DD]; // [sp][b][g][e][d]
__device__ __half g_xh[(size_t)NN * CCH];
__device__ __half g_ah[(size_t)NN * EE];
__device__ __half g_wqvh[(size_t)NQV * CCH];
__device__ __half g_woh[(size_t)CCH * EE];
__device__ float g_bqv[NQV];

// ---------------------------------------------------------------------------
// PTX wrappers (sm_80-baseline only)
// ---------------------------------------------------------------------------
__device__ __forceinline__ uint32_t smem_u32(const void* p) {
    uint32_t a;
    asm("{ .reg .u64 t; cvta.to.shared.u64 t, %1; cvt.u32.u64 %0, t; }"
        : "=r"(a) : "l"(p));
    return a;
}
__device__ __forceinline__ void cp_async16(uint32_t dst, const void* src) {
    asm volatile("cp.async.cg.shared.global [%0], [%1], 16;"
                 :: "r"(dst), "l"(src));
}
__device__ __forceinline__ void cp_commit() {
    asm volatile("cp.async.commit_group;");
}
__device__ __forceinline__ void cp_wait2() {
    asm volatile("cp.async.wait_group 2;");
}
__device__ __forceinline__ void cp_wait1() {
    asm volatile("cp.async.wait_group 1;");
}
__device__ __forceinline__ void cp_wait0() {
    asm volatile("cp.async.wait_group 0;");
}
__device__ __forceinline__ void ldm4(uint32_t* r, uint32_t addr) {
    asm volatile("ldmatrix.sync.aligned.m8n8.x4.shared.b16 {%0,%1,%2,%3}, [%4];"
                 : "=r"(r[0]), "=r"(r[1]), "=r"(r[2]), "=r"(r[3]) : "r"(addr));
}
__device__ __forceinline__ void mma_f16(float* c, const uint32_t* a,
                                        const uint32_t b0, const uint32_t b1) {
    asm volatile(
        "mma.sync.aligned.m16n8k16.row.col.f32.f16.f16.f32 "
        "{%0,%1,%2,%3}, {%4,%5,%6,%7}, {%8,%9}, {%0,%1,%2,%3};"
        : "+f"(c[0]), "+f"(c[1]), "+f"(c[2]), "+f"(c[3])
        : "r"(a[0]), "r"(a[1]), "r"(a[2]), "r"(a[3]), "r"(b0), "r"(b1));
}

// ---------------------------------------------------------------------------
// Pipelined fp16 tensor GEMM (R12 config — best measured).
// mode 1: QV projection + RoPE epilogue -> fp16 q/k/v.
// mode 0: Wo GEMM -> fp32 out.
// ---------------------------------------------------------------------------
#define NSTAGE 4
#define STAGE_BYTES 16384
#define GEMM_SMEM (NSTAGE * STAGE_BYTES)

__global__ __launch_bounds__(256, 2) void gemm_mma(
    const __half* __restrict__ Ah, const __half* __restrict__ Bh,
    const float* __restrict__ bias,
    __half* __restrict__ qh, __half* __restrict__ vh, __half* __restrict__ kh,
    float* __restrict__ outF,
    const float* __restrict__ pos, const float* __restrict__ freqs,
    int kTot, int mode)
{
    extern __shared__ char smem[];
    const uint32_t uS = smem_u32(smem);

    const int tid = threadIdx.x;
    const int bm = blockIdx.y * 128;
    const int bn = blockIdx.x * 128;

    const int lrow = tid >> 1;
    const int lc = (tid & 1) * 2;
    const char* gA_h = (const char*)(Ah + (size_t)(bm + lrow) * kTot);
    const char* gB_h = (const char*)(Bh + (size_t)(bn + lrow) * kTot);
    uint32_t sw[2];
#pragma unroll
    for (int i = 0; i < 2; i++)
        sw[i] = SW64((uint32_t)lrow * 64 + (lc + i) * 16);

    const int wid = tid >> 5, lane = tid & 31;
    const int wm = (wid & 3) * 32;
    const int wn = (wid >> 2) * 64;

    const uint32_t aRowOff = (uint32_t)(wm + (lane & 15)) * 64;
    const uint32_t aByte = (uint32_t)(lane >> 4) * 16;
    const uint32_t bRowOff =
        (uint32_t)(wn + ((lane >> 4) << 3) + (lane & 7)) * 64;
    const uint32_t bByte = (uint32_t)((lane >> 3) & 1) * 16;

    float acc[2][8][4];
#pragma unroll
    for (int mt = 0; mt < 2; mt++)
#pragma unroll
        for (int nt = 0; nt < 8; nt++)
#pragma unroll
            for (int j = 0; j < 4; j++) acc[mt][nt][j] = 0.f;

    const int nIter = kTot / 32;

    // prologue: stages 0..2
#pragma unroll
    for (int s = 0; s < 3; s++) {
        const uint32_t sb = uS + s * STAGE_BYTES;
        const int k0b = s * 64;
#pragma unroll
        for (int i = 0; i < 2; i++) {
            const int go = k0b + (lc + i) * 16;
            cp_async16(sb + sw[i], gA_h + go);
            cp_async16(sb + 8192 + sw[i], gB_h + go);
        }
        cp_commit();
    }

    int st = 0, ld = 3;
    for (int c = 0; c < nIter; c++) {
        if (c + 3 < nIter) {
            const uint32_t sb = uS + ld * STAGE_BYTES;
            const int k0b = (c + 3) * 64;
#pragma unroll
            for (int i = 0; i < 2; i++) {
                const int go = k0b + (lc + i) * 16;
                cp_async16(sb + sw[i], gA_h + go);
                cp_async16(sb + 8192 + sw[i], gB_h + go);
            }
            cp_commit();
            asm volatile("cp.async.wait_group 3;");
        } else {
            const int rem = nIter - 1 - c;
            if (rem == 2) cp_wait2();
            else if (rem == 1) cp_wait1();
            else cp_wait0();
        }
        __syncthreads();

        const uint32_t base = uS + st * STAGE_BYTES;
        const uint32_t uAh = base;
        const uint32_t uBh = base + 8192;

#pragma unroll
        for (int ks = 0; ks < 2; ks++) {
            const uint32_t kb = (uint32_t)ks * 32;
            uint32_t ax[2][4], bx[4][4];
#pragma unroll
            for (int mt = 0; mt < 2; mt++)
                ldm4(ax[mt], uAh + SW64(aRowOff + mt * 1024 + kb + aByte));
#pragma unroll
            for (int nt2 = 0; nt2 < 4; nt2++)
                ldm4(bx[nt2], uBh + SW64(bRowOff + nt2 * 1024 + kb + bByte));
#pragma unroll
            for (int mt = 0; mt < 2; mt++)
#pragma unroll
                for (int nt = 0; nt < 8; nt++)
                    mma_f16(acc[mt][nt], ax[mt],
                            bx[nt >> 1][(nt & 1) * 2], bx[nt >> 1][(nt & 1) * 2 + 1]);
        }
        __syncthreads();
        st = (st == NSTAGE - 1) ? 0 : st + 1;
        ld = (ld == NSTAGE - 1) ? 0 : ld + 1;
    }

    // ------------------------- epilogue -------------------------
    const int r0 = bm + wm + (lane >> 2);
    const int cb = wn + (lane & 3) * 2;

    if (mode == 1 && bn < EE) {
        // Q half: bias + RoPE -> fp16 q_rot and k_rot
        float px[4], py[4], pz[4];
        int rr[4];
#pragma unroll
        for (int j = 0; j < 4; j++) {
            rr[j] = r0 + (j >> 1) * 16 + (j & 1) * 8;
            px[j] = pos[rr[j] * 3 + 0];
            py[j] = pos[rr[j] * 3 + 1];
            pz[j] = pos[rr[j] * 3 + 2];
        }
#pragma unroll
        for (int nt = 0; nt < 8; nt++) {
            const int gc = bn + cb + nt * 8;          // even global column
            const int g = gc >> 5;
            const int p = (gc & 31) >> 1;
            const float* f = freqs + ((size_t)g * PPAIR + p) * 3;
            const float fx = f[0], fy = f[1], fz = f[2];
            const float b0 = bias[gc], b1 = bias[gc + 1];
#pragma unroll
            for (int mt = 0; mt < 2; mt++) {
#pragma unroll
                for (int h = 0; h < 2; h++) {
                    const int j = mt * 2 + h;
                    const float ph = px[j] * fx + py[j] * fy + pz[j] * fz;
                    const float sn = __sinf(ph);
                    const float cs = __cosf(ph);
                    const float x1 = acc[mt][nt][h * 2 + 0] + b0;
                    const float x2 = acc[mt][nt][h * 2 + 1] + b1;
                    const size_t o = (size_t)rr[j] * EE + gc;
                    *(__half2*)&qh[o] =
                        __floats2half2_rn(x1 * cs - x2 * sn, x1 * sn + x2 * cs);
                    *(__half2*)&kh[o] = __floats2half2_rn(cs - sn, sn + cs);
                }
            }
        }
    } else if (mode == 1) {
        // V half -> fp16
        const int bcol = bn - EE;
#pragma unroll
        for (int mt = 0; mt < 2; mt++) {
            const int row = r0 + mt * 16;
#pragma unroll
            for (int nt = 0; nt < 8; nt++) {
                const int col = cb + nt * 8;
                const float b0 = bias[bn + col];
                const float b1 = bias[bn + col + 1];
                *(__half2*)&vh[(size_t)row * EE + bcol + col] =
                    __floats2half2_rn(acc[mt][nt][0] + b0, acc[mt][nt][1] + b1);
                *(__half2*)&vh[(size_t)(row + 8) * EE + bcol + col] =
                    __floats2half2_rn(acc[mt][nt][2] + b0, acc[mt][nt][3] + b1);
            }
        }
    } else {
        // Wo GEMM: fp32 out
#pragma unroll
        for (int mt = 0; mt < 2; mt++) {
            const int row = r0 + mt * 16;
#pragma unroll
            for (int nt = 0; nt < 8; nt++) {
                const int col = cb + nt * 8;
                const float b0 = bias[bn + col];
                const float b1 = bias[bn + col + 1];
                float2 v0, v1;
                v0.x = acc[mt][nt][0] + b0; v0.y = acc[mt][nt][1] + b1;
                v1.x = acc[mt][nt][2] + b0; v1.y = acc[mt][nt][3] + b1;
                *(float2*)&outF[(size_t)row * EE + bn + col]       = v0;
                *(float2*)&outF[(size_t)(row + 8) * EE + bn + col] = v1;
            }
        }
    }
}

// ---------------------------------------------------------------------------
// Merged prep: x -> fp16; weight transpose (fp16); bias pack
// ---------------------------------------------------------------------------
#define CONV_T (NN * CCH / 4)
__global__ void prep_kernel(const float* __restrict__ x,
                            const float* __restrict__ Wq,
                            const float* __restrict__ Wv,
                            const float* __restrict__ Wo,
                            const float* __restrict__ bq,
                            const float* __restrict__ bv)
{
    int t = blockIdx.x * blockDim.x + threadIdx.x;
    if (t < CONV_T) {
        int i = t * 4;
        float4 v = *(const float4*)(x + i);
        *(__half2*)(g_xh + i)     = __floats2half2_rn(v.x, v.y);
        *(__half2*)(g_xh + i + 2) = __floats2half2_rn(v.z, v.w);
        return;
    }
    int idx = t - CONV_T;
    const int T1 = NQV * CCH;
    if (idx < T1) {
        int n = idx / CCH, k = idx % CCH;
        float f = (n < EE) ? Wq[(size_t)k * EE + n] : Wv[(size_t)k * EE + (n - EE)];
        g_wqvh[idx] = __float2half_rn(f);
    } else if (idx < T1 + CCH * EE) {
        int j = idx - T1;
        int n = j / EE, k = j % EE;
        g_woh[j] = __float2half_rn(Wo[(size_t)k * CCH + n]);
    }
    if (idx < NQV) g_bqv[idx] = (idx < EE) ? bq[idx] : bv[idx - EE];
}

// ---------------------------------------------------------------------------
// Inline segment bound (batch is sorted)
// ---------------------------------------------------------------------------
__device__ __forceinline__ int seg_lower(const int* __restrict__ batch, int t)
{
    int lo = 0, hi = NN;
    while (lo < hi) {
        int mid = (lo + hi) >> 1;
        if (batch[mid] < t) lo = mid + 1; else hi = mid;
    }
    return lo;
}

// ---------------------------------------------------------------------------
// KV segment reduction (fp16 inputs): emits kvT[sp][b][g][e][d] (fp32).
// ---------------------------------------------------------------------------
#define KVCH 16
__global__ __launch_bounds__(256) void kv_kernel(const int* __restrict__ batch)
{
    const int bx = blockIdx.x;
    const int gt = bx % 3;
    const int sp = bx / 3;
    const int b = blockIdx.y;
    const int s = seg_lower(batch, b);
    const int e = seg_lower(batch, b + 1);
    const int len = e - s;
    const int per = (len + KVSPLIT - 1) / KVSPLIT;
    const int rs = s + sp * per;
    const int re = min(e, rs + per);

    const int tid = threadIdx.x;
    const int gq = tid >> 6;
    const int t64 = tid & 63;
    const int d4 = ((t64 >> 3) & 7) * 4;
    const int e4 = (t64 & 7) * 4;
    const int g = gt * 4 + gq;
    const int cbase = gq * DD;

    __shared__ __half sk[2][KVCH][128];   // 4KB each stage-half
    __shared__ __half sv[2][KVCH][128];

    // SWAP: stage v into sk, k into sv -> acc = v_i * k_j -> [e][d]
    const __half* __restrict__ karr = g_vh;
    const __half* __restrict__ varr = g_kh;

    float acc[4][4];
#pragma unroll
    for (int i = 0; i < 4; i++)
#pragma unroll
        for (int j = 0; j < 4; j++) acc[i][j] = 0.f;

    if (rs < re) {
        const int gcol = gt * 128;   // half offset of 4-group slice

        // loader: per stage per array 16 nodes x 128 halves = 256 x 16B;
        // both arrays = 512 x 16B; 2 per thread.
#pragma unroll
        for (int j = 0; j < 2; j++) {
            const int i = tid + j * 256;
            const int arr = i >> 8;
            const int r = i & 255;
            const int node = r >> 4;
            const int c16 = r & 15;
            if (rs + node < re) {
                const __half* src = (arr ? varr : karr)
                    + (size_t)(rs + node) * CCH + gcol + c16 * 8;
                const uint32_t dst = smem_u32(
                    arr ? &sv[0][node][c16 * 8] : &sk[0][node][c16 * 8]);
                cp_async16(dst, src);
            }
        }
        cp_commit();

        int st = 0;
        for (int n0 = rs; n0 < re; n0 += KVCH, st ^= 1) {
            const int nn = n0 + KVCH;
            if (nn < re) {
                const int nst = st ^ 1;
#pragma unroll
                for (int j = 0; j < 2; j++) {
                    const int i = tid + j * 256;
                    const int arr = i >> 8;
                    const int r = i & 255;
                    const int node = r >> 4;
                    const int c16 = r & 15;
                    if (nn + node < re) {
                        const __half* src = (arr ? varr : karr)
                            + (size_t)(nn + node) * CCH + gcol + c16 * 8;
                        const uint32_t dst = smem_u32(
                            arr ? &sv[nst][node][c16 * 8] : &sk[nst][node][c16 * 8]);
                        cp_async16(dst, src);
                    }
                }
                cp_commit();
                cp_wait1();
            } else {
                cp_wait0();
            }
            __syncthreads();
            const int cnt = min(KVCH, re - n0);
            for (int c = 0; c < cnt; c++) {
                const __half2* k2 = (const __half2*)&sk[st][c][cbase + d4];
                const __half2* v2 = (const __half2*)&sv[st][c][cbase + e4];
                const float2 k01 = __half22float2(k2[0]);
                const float2 k23 = __half22float2(k2[1]);
                const float2 v01 = __half22float2(v2[0]);
                const float2 v23 = __half22float2(v2[1]);
                acc[0][0] += k01.x * v01.x; acc[0][1] += k01.x * v01.y;
                acc[0][2] += k01.x * v23.x; acc[0][3] += k01.x * v23.y;
                acc[1][0] += k01.y * v01.x; acc[1][1] += k01.y * v01.y;
                acc[1][2] += k01.y * v23.x; acc[1][3] += k01.y * v23.y;
                acc[2][0] += k23.x * v01.x; acc[2][1] += k23.x * v01.y;
                acc[2][2] += k23.x * v23.x; acc[2][3] += k23.x * v23.y;
                acc[3][0] += k23.y * v01.x; acc[3][1] += k23.y * v01.y;
                acc[3][2] += k23.y * v23.x; acc[3][3] += k23.y * v23.y;
            }
            __syncthreads();
        }
    }

    float* dst = g_kv
        + ((((size_t)sp * NGRAPH + b) * GG + g) * DD + d4) * DD + e4;
#pragma unroll
    for (int i = 0; i < 4; i++) {
        float4 o;
        o.x = acc[i][0]; o.y = acc[i][1]; o.z = acc[i][2]; o.w = acc[i][3];
        *(float4*)(dst + (size_t)i * DD) = o;
    }
}

// ---------------------------------------------------------------------------
// Apply: warp-per-group, kv column in registers; fp16 q in, fp16 out.
// 8 node-splits per graph (512 blocks).
// ---------------------------------------------------------------------------
#define AQN 16
#define ASPLIT 8
__global__ __launch_bounds__(384) void attn_kernel(const int* __restrict__ batch)
{
    const int c = blockIdx.x;
    const int b = blockIdx.y;
    const int s = seg_lower(batch, b);
    const int e = seg_lower(batch, b + 1);
    const int len = e - s;
    const int per = (len + ASPLIT - 1) / ASPLIT;
    const int rs = s + c * per;
    const int re = min(e, rs + per);
    if (rs >= re) return;

    const int tid = threadIdx.x;
    const int g = tid >> 5;
    const int lane = tid & 31;

    float kvc[DD];
    {
        const float inv = 1.0f / 512.0f;
        const size_t spStride = (size_t)NGRAPH * GG * DD * DD;
        const float* p0 = g_kv + (((size_t)b * GG + g) * DD + lane) * DD;
#pragma unroll
        for (int d = 0; d < DD; d += 4) {
            float4 a0 = *(const float4*)(p0 + d);
            float4 a1 = *(const float4*)(p0 + spStride + d);
            float4 a2 = *(const float4*)(p0 + 2 * spStride + d);
            float4 a3 = *(const float4*)(p0 + 3 * spStride + d);
            kvc[d + 0] = (a0.x + a1.x + a2.x + a3.x) * inv;
            kvc[d + 1] = (a0.y + a1.y + a2.y + a3.y) * inv;
            kvc[d + 2] = (a0.z + a1.z + a2.z + a3.z) * inv;
            kvc[d + 3] = (a0.w + a1.w + a2.w + a3.w) * inv;
        }
    }

    __shared__ __half qs[2][AQN][EE];   // 2 x 12 KB

    // loader: AQN x 384 halves = 768 x 16B per stage; 384 threads x 2
#pragma unroll
    for (int k = 0; k < 2; k++) {
        const int idx = tid + k * 384;
        const int node = idx / 48;
        const int c16 = idx % 48;
        if (rs + node < re)
            cp_async16(smem_u32(&qs[0][node][c16 * 8]),
                       g_qh + (size_t)(rs + node) * EE + c16 * 8);
    }
    cp_commit();

    int st = 0;
    for (int n0 = rs; n0 < re; n0 += AQN, st ^= 1) {
        const int nn = n0 + AQN;
        if (nn < re) {
            const int nst = st ^ 1;
#pragma unroll
            for (int k = 0; k < 2; k++) {
                const int idx = tid + k * 384;
                const int node = idx / 48;
                const int c16 = idx % 48;
                if (nn + node < re)
                    cp_async16(smem_u32(&qs[nst][node][c16 * 8]),
                               g_qh + (size_t)(nn + node) * EE + c16 * 8);
            }
            cp_commit();
            cp_wait1();
        } else {
            cp_wait0();
        }
        __syncthreads();

        const int cnt = min(AQN, re - n0);
        for (int i = 0; i < cnt; i++) {
            const __half2* q2 = (const __half2*)&qs[st][i][g * DD];
            float sum = 0.f;
#pragma unroll
            for (int d = 0; d < DD / 2; d++) {
                const float2 qf = __half22float2(q2[d]);
                sum += qf.x * kvc[2 * d] + qf.y * kvc[2 * d + 1];
            }
            g_ah[(size_t)(n0 + i) * EE + g * DD + lane] = __float2half_rn(sum);
        }
        __syncthreads();
    }
}

// ---------------------------------------------------------------------------
// Launch
// ---------------------------------------------------------------------------
extern "C" void kernel_launch(void* const* d_in, const int* in_sizes, int n_in,
                              void* d_out, int out_size)
{
    const float* x     = (const float*)d_in[0];
    const float* pos   = (const float*)d_in[1];
    const int*   batch = (const int*)d_in[2];
    const float* Wq    = (const float*)d_in[3];
    const float* bq    = (const float*)d_in[4];
    const float* Wv    = (const float*)d_in[5];
    const float* bv    = (const float*)d_in[6];
    const float* Wo    = (const float*)d_in[7];
    const float* bo    = (const float*)d_in[8];
    const float* freqs = (const float*)d_in[9];
    float* out = (float*)d_out;

    float *gbqv;
    __half *gqh, *gvh, *gkh, *gxh, *gah, *gwqvh, *gwoh;
    cudaGetSymbolAddress((void**)&gqh, g_qh);
    cudaGetSymbolAddress((void**)&gvh, g_vh);
    cudaGetSymbolAddress((void**)&gkh, g_kh);
    cudaGetSymbolAddress((void**)&gbqv, g_bqv);
    cudaGetSymbolAddress((void**)&gxh, g_xh);
    cudaGetSymbolAddress((void**)&gah, g_ah);
    cudaGetSymbolAddress((void**)&gwqvh, g_wqvh);
    cudaGetSymbolAddress((void**)&gwoh, g_woh);

    cudaFuncSetAttribute(gemm_mma,
                         cudaFuncAttributeMaxDynamicSharedMemorySize, GEMM_SMEM);

    // 1) merged prep: x -> fp16, weight transpose, bias pack
    const int prepT = CONV_T + NQV * CCH + CCH * EE;
    prep_kernel<<<(prepT + 255) / 256, 256>>>(x, Wq, Wv, Wo, bq, bv);

    // 2) fused QV projection + RoPE epilogue -> fp16 g_qh, g_kh, g_vh
    gemm_mma<<<dim3(NQV / 128, NN / 128), 256, GEMM_SMEM>>>(
        gxh, gwqvh, gbqv, gqh, gvh, gkh, nullptr, pos, freqs, CCH, 1);

    // 3) kvT = segsum(v outer k) per node-split -> [sp][b][g][e][d]
    kv_kernel<<<dim3(3 * KVSPLIT, NGRAPH), 256>>>(batch);

    // 4) attn = q . kv[batch]/512 -> fp16
    attn_kernel<<<dim3(ASPLIT, NGRAPH), 384>>>(batch);

    // 5) out = attn @ Wo + bo
    gemm_mma<<<dim3(EE / 128, NN / 128), 256, GEMM_SMEM>>>(
        gah, gwoh, bo, nullptr, nullptr, nullptr, out, nullptr, nullptr, EE, 0);
}

// round 16
// speedup vs baseline: 1.0553x; 1.0553x over previous
#include <cuda_runtime.h>
#include <cuda_fp16.h>
#include <cstdint>
#include <cstddef>

// Problem constants
#define NN 32768
#define CCH 384
#define EE 384
#define GG 12
#define DD 32
#define PPAIR 16
#define NGRAPH 64
#define NQV 768

#define SW64(off) ((off) ^ (((off) >> 3) & 0x30))

// ---------------------------------------------------------------------------
// Scratch
// ---------------------------------------------------------------------------
#define KVSPLIT 4
__device__ float g_q[(size_t)NN * EE];
__device__ float g_v[(size_t)NN * EE];
__device__ float g_k[(size_t)NN * EE];
__device__ float g_kv[(size_t)KVSPLIT * NGRAPH * GG * DD * DD]; // [sp][b][g][e][d]
__device__ __half g_xh[(size_t)NN * CCH];
__device__ __half g_ah[(size_t)NN * EE];
__device__ __half g_wqvh[(size_t)NQV * CCH];
__device__ __half g_woh[(size_t)CCH * EE];
__device__ float g_bqv[NQV];

// ---------------------------------------------------------------------------
// PTX wrappers (sm_80-baseline only)
// ---------------------------------------------------------------------------
__device__ __forceinline__ uint32_t smem_u32(const void* p) {
    uint32_t a;
    asm("{ .reg .u64 t; cvta.to.shared.u64 t, %1; cvt.u32.u64 %0, t; }"
        : "=r"(a) : "l"(p));
    return a;
}
__device__ __forceinline__ void cp_async16(uint32_t dst, const void* src) {
    asm volatile("cp.async.cg.shared.global [%0], [%1], 16;"
                 :: "r"(dst), "l"(src));
}
__device__ __forceinline__ void cp_commit() {
    asm volatile("cp.async.commit_group;");
}
__device__ __forceinline__ void cp_wait2() {
    asm volatile("cp.async.wait_group 2;");
}
__device__ __forceinline__ void cp_wait1() {
    asm volatile("cp.async.wait_group 1;");
}
__device__ __forceinline__ void cp_wait0() {
    asm volatile("cp.async.wait_group 0;");
}
__device__ __forceinline__ void ldm4(uint32_t* r, uint32_t addr) {
    asm volatile("ldmatrix.sync.aligned.m8n8.x4.shared.b16 {%0,%1,%2,%3}, [%4];"
                 : "=r"(r[0]), "=r"(r[1]), "=r"(r[2]), "=r"(r[3]) : "r"(addr));
}
__device__ __forceinline__ void mma_f16(float* c, const uint32_t* a,
                                        const uint32_t b0, const uint32_t b1) {
    asm volatile(
        "mma.sync.aligned.m16n8k16.row.col.f32.f16.f16.f32 "
        "{%0,%1,%2,%3}, {%4,%5,%6,%7}, {%8,%9}, {%0,%1,%2,%3};"
        : "+f"(c[0]), "+f"(c[1]), "+f"(c[2]), "+f"(c[3])
        : "r"(a[0]), "r"(a[1]), "r"(a[2]), "r"(a[3]), "r"(b0), "r"(b1));
}

// ---------------------------------------------------------------------------
// Pipelined fp16 tensor GEMM (R12 config — best measured).
// mode 1 = QV projection with RoPE fused into Q-half epilogue. fp32 outs.
// ---------------------------------------------------------------------------
#define NSTAGE 4
#define STAGE_BYTES 16384
#define GEMM_SMEM (NSTAGE * STAGE_BYTES)

__global__ __launch_bounds__(256, 2) void gemm_mma(
    const __half* __restrict__ Ah, const __half* __restrict__ Bh,
    const float* __restrict__ bias, float* __restrict__ outQ,
    float* __restrict__ outV, float* __restrict__ outK,
    const float* __restrict__ pos, const float* __restrict__ freqs,
    int kTot, int mode)
{
    extern __shared__ char smem[];
    const uint32_t uS = smem_u32(smem);

    const int tid = threadIdx.x;
    const int bm = blockIdx.y * 128;
    const int bn = blockIdx.x * 128;

    const int lrow = tid >> 1;
    const int lc = (tid & 1) * 2;
    const char* gA_h = (const char*)(Ah + (size_t)(bm + lrow) * kTot);
    const char* gB_h = (const char*)(Bh + (size_t)(bn + lrow) * kTot);
    uint32_t sw[2];
#pragma unroll
    for (int i = 0; i < 2; i++)
        sw[i] = SW64((uint32_t)lrow * 64 + (lc + i) * 16);

    const int wid = tid >> 5, lane = tid & 31;
    const int wm = (wid & 3) * 32;
    const int wn = (wid >> 2) * 64;

    const uint32_t aRowOff = (uint32_t)(wm + (lane & 15)) * 64;
    const uint32_t aByte = (uint32_t)(lane >> 4) * 16;
    const uint32_t bRowOff =
        (uint32_t)(wn + ((lane >> 4) << 3) + (lane & 7)) * 64;
    const uint32_t bByte = (uint32_t)((lane >> 3) & 1) * 16;

    float acc[2][8][4];
#pragma unroll
    for (int mt = 0; mt < 2; mt++)
#pragma unroll
        for (int nt = 0; nt < 8; nt++)
#pragma unroll
            for (int j = 0; j < 4; j++) acc[mt][nt][j] = 0.f;

    const int nIter = kTot / 32;

    // prologue: stages 0..2
#pragma unroll
    for (int s = 0; s < 3; s++) {
        const uint32_t sb = uS + s * STAGE_BYTES;
        const int k0b = s * 64;
#pragma unroll
        for (int i = 0; i < 2; i++) {
            const int go = k0b + (lc + i) * 16;
            cp_async16(sb + sw[i], gA_h + go);
            cp_async16(sb + 8192 + sw[i], gB_h + go);
        }
        cp_commit();
    }

    int st = 0, ld = 3;
    for (int c = 0; c < nIter; c++) {
        if (c + 3 < nIter) {
            const uint32_t sb = uS + ld * STAGE_BYTES;
            const int k0b = (c + 3) * 64;
#pragma unroll
            for (int i = 0; i < 2; i++) {
                const int go = k0b + (lc + i) * 16;
                cp_async16(sb + sw[i], gA_h + go);
                cp_async16(sb + 8192 + sw[i], gB_h + go);
            }
            cp_commit();
            asm volatile("cp.async.wait_group 3;");
        } else {
            const int rem = nIter - 1 - c;
            if (rem == 2) cp_wait2();
            else if (rem == 1) cp_wait1();
            else cp_wait0();
        }
        __syncthreads();

        const uint32_t base = uS + st * STAGE_BYTES;
        const uint32_t uAh = base;
        const uint32_t uBh = base + 8192;

#pragma unroll
        for (int ks = 0; ks < 2; ks++) {
            const uint32_t kb = (uint32_t)ks * 32;
            uint32_t ax[2][4], bx[4][4];
#pragma unroll
            for (int mt = 0; mt < 2; mt++)
                ldm4(ax[mt], uAh + SW64(aRowOff + mt * 1024 + kb + aByte));
#pragma unroll
            for (int nt2 = 0; nt2 < 4; nt2++)
                ldm4(bx[nt2], uBh + SW64(bRowOff + nt2 * 1024 + kb + bByte));
#pragma unroll
            for (int mt = 0; mt < 2; mt++)
#pragma unroll
                for (int nt = 0; nt < 8; nt++)
                    mma_f16(acc[mt][nt], ax[mt],
                            bx[nt >> 1][(nt & 1) * 2], bx[nt >> 1][(nt & 1) * 2 + 1]);
        }
        __syncthreads();
        st = (st == NSTAGE - 1) ? 0 : st + 1;
        ld = (ld == NSTAGE - 1) ? 0 : ld + 1;
    }

    // ------------------------- epilogue -------------------------
    const int r0 = bm + wm + (lane >> 2);
    const int cb = wn + (lane & 3) * 2;

    if (mode == 1 && bn < EE) {
        float px[4], py[4], pz[4];
        int rr[4];
#pragma unroll
        for (int j = 0; j < 4; j++) {
            rr[j] = r0 + (j >> 1) * 16 + (j & 1) * 8;
            px[j] = pos[rr[j] * 3 + 0];
            py[j] = pos[rr[j] * 3 + 1];
            pz[j] = pos[rr[j] * 3 + 2];
        }
#pragma unroll
        for (int nt = 0; nt < 8; nt++) {
            const int gc = bn + cb + nt * 8;          // even global column
            const int g = gc >> 5;
            const int p = (gc & 31) >> 1;
            const float* f = freqs + ((size_t)g * PPAIR + p) * 3;
            const float fx = f[0], fy = f[1], fz = f[2];
            const float b0 = bias[gc], b1 = bias[gc + 1];
#pragma unroll
            for (int mt = 0; mt < 2; mt++) {
#pragma unroll
                for (int h = 0; h < 2; h++) {
                    const int j = mt * 2 + h;
                    const float ph = px[j] * fx + py[j] * fy + pz[j] * fz;
                    const float sn = __sinf(ph);
                    const float cs = __cosf(ph);
                    const float x1 = acc[mt][nt][h * 2 + 0] + b0;
                    const float x2 = acc[mt][nt][h * 2 + 1] + b1;
                    float2 qv, kv;
                    qv.x = x1 * cs - x2 * sn;
                    qv.y = x1 * sn + x2 * cs;
                    kv.x = cs - sn;
                    kv.y = sn + cs;
                    const size_t o = (size_t)rr[j] * EE + gc;
                    *(float2*)&outQ[o] = qv;
                    *(float2*)&outK[o] = kv;
                }
            }
        }
    } else {
        float* dst = (mode == 1) ? outV : outQ;
        const int bcol = (mode == 1) ? bn - EE : bn;
#pragma unroll
        for (int mt = 0; mt < 2; mt++) {
            const int row = r0 + mt * 16;
#pragma unroll
            for (int nt = 0; nt < 8; nt++) {
                const int col = cb + nt * 8;
                const float b0 = bias[bn + col];
                const float b1 = bias[bn + col + 1];
                float2 v0, v1;
                v0.x = acc[mt][nt][0] + b0; v0.y = acc[mt][nt][1] + b1;
                v1.x = acc[mt][nt][2] + b0; v1.y = acc[mt][nt][3] + b1;
                *(float2*)&dst[(size_t)row * EE + bcol + col]       = v0;
                *(float2*)&dst[(size_t)(row + 8) * EE + bcol + col] = v1;
            }
        }
    }
}

// ---------------------------------------------------------------------------
// Merged prep: x -> fp16; weight transpose (fp16); bias pack
// ---------------------------------------------------------------------------
#define CONV_T (NN * CCH / 4)
__global__ void prep_kernel(const float* __restrict__ x,
                            const float* __restrict__ Wq,
                            const float* __restrict__ Wv,
                            const float* __restrict__ Wo,
                            const float* __restrict__ bq,
                            const float* __restrict__ bv)
{
    int t = blockIdx.x * blockDim.x + threadIdx.x;
    if (t < CONV_T) {
        int i = t * 4;
        float4 v = *(const float4*)(x + i);
        *(__half2*)(g_xh + i)     = __floats2half2_rn(v.x, v.y);
        *(__half2*)(g_xh + i + 2) = __floats2half2_rn(v.z, v.w);
        return;
    }
    int idx = t - CONV_T;
    const int T1 = NQV * CCH;
    if (idx < T1) {
        int n = idx / CCH, k = idx % CCH;
        float f = (n < EE) ? Wq[(size_t)k * EE + n] : Wv[(size_t)k * EE + (n - EE)];
        g_wqvh[idx] = __float2half_rn(f);
    } else if (idx < T1 + CCH * EE) {
        int j = idx - T1;
        int n = j / EE, k = j % EE;
        g_woh[j] = __float2half_rn(Wo[(size_t)k * CCH + n]);
    }
    if (idx < NQV) g_bqv[idx] = (idx < EE) ? bq[idx] : bv[idx - EE];
}

// ---------------------------------------------------------------------------
// Inline segment bound (batch is sorted)
// ---------------------------------------------------------------------------
__device__ __forceinline__ int seg_lower(const int* __restrict__ batch, int t)
{
    int lo = 0, hi = NN;
    while (lo < hi) {
        int mid = (lo + hi) >> 1;
        if (batch[mid] < t) lo = mid + 1; else hi = mid;
    }
    return lo;
}

// ---------------------------------------------------------------------------
// KV segment reduction (R14/R12): emits kvT[sp][b][g][e][d] (fp32 in/out).
// ---------------------------------------------------------------------------
#define KVCH 16
__global__ __launch_bounds__(256) void kv_kernel(const int* __restrict__ batch)
{
    const int bx = blockIdx.x;
    const int gt = bx % 3;
    const int sp = bx / 3;
    const int b = blockIdx.y;
    const int s = seg_lower(batch, b);
    const int e = seg_lower(batch, b + 1);
    const int len = e - s;
    const int per = (len + KVSPLIT - 1) / KVSPLIT;
    const int rs = s + sp * per;
    const int re = min(e, rs + per);

    const int tid = threadIdx.x;
    const int gq = tid >> 6;
    const int t64 = tid & 63;
    const int d4 = ((t64 >> 3) & 7) * 4;
    const int e4 = (t64 & 7) * 4;
    const int g = gt * 4 + gq;
    const int cbase = gq * DD;

    __shared__ float sk[2][KVCH][128];
    __shared__ float sv[2][KVCH][128];

    // SWAP: stage v into sk, k into sv -> acc = v_i * k_j -> [e][d]
    const float* __restrict__ karr = g_v;
    const float* __restrict__ varr = g_k;

    float acc[4][4];
#pragma unroll
    for (int i = 0; i < 4; i++)
#pragma unroll
        for (int j = 0; j < 4; j++) acc[i][j] = 0.f;

    if (rs < re) {
        const int gcol = gt * 128;

#pragma unroll
        for (int j = 0; j < 4; j++) {
            const int i = tid + j * 256;
            const int arr = i >> 9;
            const int r = i & 511;
            const int node = r >> 5;
            const int c4 = r & 31;
            if (rs + node < re) {
                const float* src = (arr ? varr : karr)
                    + (size_t)(rs + node) * CCH + gcol + c4 * 4;
                const uint32_t dst = smem_u32(
                    arr ? &sv[0][node][c4 * 4] : &sk[0][node][c4 * 4]);
                cp_async16(dst, src);
            }
        }
        cp_commit();

        int st = 0;
        for (int n0 = rs; n0 < re; n0 += KVCH, st ^= 1) {
            const int nn = n0 + KVCH;
            if (nn < re) {
                const int nst = st ^ 1;
#pragma unroll
                for (int j = 0; j < 4; j++) {
                    const int i = tid + j * 256;
                    const int arr = i >> 9;
                    const int r = i & 511;
                    const int node = r >> 5;
                    const int c4 = r & 31;
                    if (nn + node < re) {
                        const float* src = (arr ? varr : karr)
                            + (size_t)(nn + node) * CCH + gcol + c4 * 4;
                        const uint32_t dst = smem_u32(
                            arr ? &sv[nst][node][c4 * 4] : &sk[nst][node][c4 * 4]);
                        cp_async16(dst, src);
                    }
                }
                cp_commit();
                cp_wait1();
            } else {
                cp_wait0();
            }
            __syncthreads();
            const int cnt = min(KVCH, re - n0);
            for (int c = 0; c < cnt; c++) {
                const float4 kk = *(const float4*)&sk[st][c][cbase + d4];
                const float4 vv = *(const float4*)&sv[st][c][cbase + e4];
                acc[0][0] += kk.x * vv.x; acc[0][1] += kk.x * vv.y;
                acc[0][2] += kk.x * vv.z; acc[0][3] += kk.x * vv.w;
                acc[1][0] += kk.y * vv.x; acc[1][1] += kk.y * vv.y;
                acc[1][2] += kk.y * vv.z; acc[1][3] += kk.y * vv.w;
                acc[2][0] += kk.z * vv.x; acc[2][1] += kk.z * vv.y;
                acc[2][2] += kk.z * vv.z; acc[2][3] += kk.z * vv.w;
                acc[3][0] += kk.w * vv.x; acc[3][1] += kk.w * vv.y;
                acc[3][2] += kk.w * vv.z; acc[3][3] += kk.w * vv.w;
            }
            __syncthreads();
        }
    }

    float* dst = g_kv
        + ((((size_t)sp * NGRAPH + b) * GG + g) * DD + d4) * DD + e4;
#pragma unroll
    for (int i = 0; i < 4; i++) {
        float4 o;
        o.x = acc[i][0]; o.y = acc[i][1]; o.z = acc[i][2]; o.w = acc[i][3];
        *(float4*)(dst + (size_t)i * DD) = o;
    }
}

// ---------------------------------------------------------------------------
// Apply: warp-per-group, kv column in registers; fp32 math, fp16 out.
// 8 node-splits (512 blocks), AQN=8, 4 partial sums for FMA-chain ILP.
// ---------------------------------------------------------------------------
#define AQN 8
#define ASPLIT 8
__global__ __launch_bounds__(384) void attn_kernel(const int* __restrict__ batch)
{
    const int c = blockIdx.x;
    const int b = blockIdx.y;
    const int s = seg_lower(batch, b);
    const int e = seg_lower(batch, b + 1);
    const int len = e - s;
    const int per = (len + ASPLIT - 1) / ASPLIT;
    const int rs = s + c * per;
    const int re = min(e, rs + per);
    if (rs >= re) return;

    const int tid = threadIdx.x;
    const int g = tid >> 5;
    const int lane = tid & 31;

    float kvc[DD];
    {
        const float inv = 1.0f / 512.0f;
        const size_t spStride = (size_t)NGRAPH * GG * DD * DD;
        const float* p0 = g_kv + (((size_t)b * GG + g) * DD + lane) * DD;
#pragma unroll
        for (int d = 0; d < DD; d += 4) {
            float4 a0 = *(const float4*)(p0 + d);
            float4 a1 = *(const float4*)(p0 + spStride + d);
            float4 a2 = *(const float4*)(p0 + 2 * spStride + d);
            float4 a3 = *(const float4*)(p0 + 3 * spStride + d);
            kvc[d + 0] = (a0.x + a1.x + a2.x + a3.x) * inv;
            kvc[d + 1] = (a0.y + a1.y + a2.y + a3.y) * inv;
            kvc[d + 2] = (a0.z + a1.z + a2.z + a3.z) * inv;
            kvc[d + 3] = (a0.w + a1.w + a2.w + a3.w) * inv;
        }
    }

    __shared__ float qs[2][AQN][CCH];   // 2 x 12 KB

    // loader: 768 float4 per stage -> 2 per thread
#pragma unroll
    for (int k = 0; k < 2; k++) {
        const int idx = tid + k * 384;
        const int node = idx / 96;
        const int c4 = idx % 96;
        if (rs + node < re)
            cp_async16(smem_u32(&qs[0][node][c4 * 4]),
                       g_q + (size_t)(rs + node) * EE + c4 * 4);
    }
    cp_commit();

    int st = 0;
    for (int n0 = rs; n0 < re; n0 += AQN, st ^= 1) {
        const int nn = n0 + AQN;
        if (nn < re) {
            const int nst = st ^ 1;
#pragma unroll
            for (int k = 0; k < 2; k++) {
                const int idx = tid + k * 384;
                const int node = idx / 96;
                const int c4 = idx % 96;
                if (nn + node < re)
                    cp_async16(smem_u32(&qs[nst][node][c4 * 4]),
                               g_q + (size_t)(nn + node) * EE + c4 * 4);
            }
            cp_commit();
            cp_wait1();
        } else {
            cp_wait0();
        }
        __syncthreads();

        const int cnt = min(AQN, re - n0);
        for (int i = 0; i < cnt; i++) {
            const float* qrow = &qs[st][i][g * DD];
            float s0 = 0.f, s1 = 0.f, s2 = 0.f, s3 = 0.f;
#pragma unroll
            for (int d = 0; d < DD; d += 4) {
                const float4 qq = *(const float4*)(qrow + d);
                s0 += qq.x * kvc[d + 0];
                s1 += qq.y * kvc[d + 1];
                s2 += qq.z * kvc[d + 2];
                s3 += qq.w * kvc[d + 3];
            }
            const float sum = (s0 + s1) + (s2 + s3);
            g_ah[(size_t)(n0 + i) * EE + g * DD + lane] = __float2half_rn(sum);
        }
        __syncthreads();
    }
}

// ---------------------------------------------------------------------------
// Launch
// ---------------------------------------------------------------------------
extern "C" void kernel_launch(void* const* d_in, const int* in_sizes, int n_in,
                              void* d_out, int out_size)
{
    const float* x     = (const float*)d_in[0];
    const float* pos   = (const float*)d_in[1];
    const int*   batch = (const int*)d_in[2];
    const float* Wq    = (const float*)d_in[3];
    const float* bq    = (const float*)d_in[4];
    const float* Wv    = (const float*)d_in[5];
    const float* bv    = (const float*)d_in[6];
    const float* Wo    = (const float*)d_in[7];
    const float* bo    = (const float*)d_in[8];
    const float* freqs = (const float*)d_in[9];
    float* out = (float*)d_out;

    float *gq, *gv, *gk, *gbqv;
    __half *gxh, *gah, *gwqvh, *gwoh;
    cudaGetSymbolAddress((void**)&gq, g_q);
    cudaGetSymbolAddress((void**)&gv, g_v);
    cudaGetSymbolAddress((void**)&gk, g_k);
    cudaGetSymbolAddress((void**)&gbqv, g_bqv);
    cudaGetSymbolAddress((void**)&gxh, g_xh);
    cudaGetSymbolAddress((void**)&gah, g_ah);
    cudaGetSymbolAddress((void**)&gwqvh, g_wqvh);
    cudaGetSymbolAddress((void**)&gwoh, g_woh);

    cudaFuncSetAttribute(gemm_mma,
                         cudaFuncAttributeMaxDynamicSharedMemorySize, GEMM_SMEM);

    // 1) merged prep: x -> fp16, weight transpose, bias pack
    const int prepT = CONV_T + NQV * CCH + CCH * EE;
    prep_kernel<<<(prepT + 255) / 256, 256>>>(x, Wq, Wv, Wo, bq, bv);

    // 2) fused QV projection + RoPE epilogue -> g_q, g_k, g_v (fp32)
    gemm_mma<<<dim3(NQV / 128, NN / 128), 256, GEMM_SMEM>>>(
        gxh, gwqvh, gbqv, gq, gv, gk, pos, freqs, CCH, 1);

    // 3) kvT = segsum(v outer k) per node-split -> [sp][b][g][e][d]
    kv_kernel<<<dim3(3 * KVSPLIT, NGRAPH), 256>>>(batch);

    // 4) attn = q . kv[batch]/512 -> fp16
    attn_kernel<<<dim3(ASPLIT, NGRAPH), 384>>>(batch);

    // 5) out = attn @ Wo + bo
    gemm_mma<<<dim3(EE / 128, NN / 128), 256, GEMM_SMEM>>>(
        gah, gwoh, bo, out, out, nullptr, nullptr, nullptr, EE, 0);
}

// round 17
// speedup vs baseline: 1.1508x; 1.0905x over previous
#include <cuda_runtime.h>
#include <cuda_fp16.h>
#include <cstdint>
#include <cstddef>

// Problem constants
#define NN 32768
#define CCH 384
#define EE 384
#define GG 12
#define DD 32
#define PPAIR 16
#define NGRAPH 64
#define NQV 768

#define SW64(off) ((off) ^ (((off) >> 3) & 0x30))

// ---------------------------------------------------------------------------
// Scratch
// ---------------------------------------------------------------------------
#define KVSPLIT 4
__device__ float g_q[(size_t)NN * EE];
__device__ float g_v[(size_t)NN * EE];
__device__ float g_k[(size_t)NN * EE];
__device__ float g_kv[(size_t)KVSPLIT * NGRAPH * GG * DD * DD]; // [sp][b][g][e][d]
__device__ float g_kvm[(size_t)NGRAPH * GG * DD * DD];          // merged+scaled
__device__ __half g_xh[(size_t)NN * CCH];
__device__ __half g_ah[(size_t)NN * EE];
__device__ __half g_wqvh[(size_t)NQV * CCH];
__device__ __half g_woh[(size_t)CCH * EE];
__device__ float g_bqv[NQV];

// ---------------------------------------------------------------------------
// PTX wrappers (sm_80-baseline only)
// ---------------------------------------------------------------------------
__device__ __forceinline__ uint32_t smem_u32(const void* p) {
    uint32_t a;
    asm("{ .reg .u64 t; cvta.to.shared.u64 t, %1; cvt.u32.u64 %0, t; }"
        : "=r"(a) : "l"(p));
    return a;
}
__device__ __forceinline__ void cp_async16(uint32_t dst, const void* src) {
    asm volatile("cp.async.cg.shared.global [%0], [%1], 16;"
                 :: "r"(dst), "l"(src));
}
__device__ __forceinline__ void cp_commit() {
    asm volatile("cp.async.commit_group;");
}
__device__ __forceinline__ void cp_wait2() {
    asm volatile("cp.async.wait_group 2;");
}
__device__ __forceinline__ void cp_wait1() {
    asm volatile("cp.async.wait_group 1;");
}
__device__ __forceinline__ void cp_wait0() {
    asm volatile("cp.async.wait_group 0;");
}
__device__ __forceinline__ void ldm4(uint32_t* r, uint32_t addr) {
    asm volatile("ldmatrix.sync.aligned.m8n8.x4.shared.b16 {%0,%1,%2,%3}, [%4];"
                 : "=r"(r[0]), "=r"(r[1]), "=r"(r[2]), "=r"(r[3]) : "r"(addr));
}
__device__ __forceinline__ void mma_f16(float* c, const uint32_t* a,
                                        const uint32_t b0, const uint32_t b1) {
    asm volatile(
        "mma.sync.aligned.m16n8k16.row.col.f32.f16.f16.f32 "
        "{%0,%1,%2,%3}, {%4,%5,%6,%7}, {%8,%9}, {%0,%1,%2,%3};"
        : "+f"(c[0]), "+f"(c[1]), "+f"(c[2]), "+f"(c[3])
        : "r"(a[0]), "r"(a[1]), "r"(a[2]), "r"(a[3]), "r"(b0), "r"(b1));
}

// ---------------------------------------------------------------------------
// Pipelined fp16 tensor GEMM (R12 config — best measured).
// mode 1 = QV projection with RoPE fused into Q-half epilogue. fp32 outs.
// ---------------------------------------------------------------------------
#define NSTAGE 4
#define STAGE_BYTES 16384
#define GEMM_SMEM (NSTAGE * STAGE_BYTES)

__global__ __launch_bounds__(256, 2) void gemm_mma(
    const __half* __restrict__ Ah, const __half* __restrict__ Bh,
    const float* __restrict__ bias, float* __restrict__ outQ,
    float* __restrict__ outV, float* __restrict__ outK,
    const float* __restrict__ pos, const float* __restrict__ freqs,
    int kTot, int mode)
{
    extern __shared__ char smem[];
    const uint32_t uS = smem_u32(smem);

    const int tid = threadIdx.x;
    const int bm = blockIdx.y * 128;
    const int bn = blockIdx.x * 128;

    const int lrow = tid >> 1;
    const int lc = (tid & 1) * 2;
    const char* gA_h = (const char*)(Ah + (size_t)(bm + lrow) * kTot);
    const char* gB_h = (const char*)(Bh + (size_t)(bn + lrow) * kTot);
    uint32_t sw[2];
#pragma unroll
    for (int i = 0; i < 2; i++)
        sw[i] = SW64((uint32_t)lrow * 64 + (lc + i) * 16);

    const int wid = tid >> 5, lane = tid & 31;
    const int wm = (wid & 3) * 32;
    const int wn = (wid >> 2) * 64;

    const uint32_t aRowOff = (uint32_t)(wm + (lane & 15)) * 64;
    const uint32_t aByte = (uint32_t)(lane >> 4) * 16;
    const uint32_t bRowOff =
        (uint32_t)(wn + ((lane >> 4) << 3) + (lane & 7)) * 64;
    const uint32_t bByte = (uint32_t)((lane >> 3) & 1) * 16;

    float acc[2][8][4];
#pragma unroll
    for (int mt = 0; mt < 2; mt++)
#pragma unroll
        for (int nt = 0; nt < 8; nt++)
#pragma unroll
            for (int j = 0; j < 4; j++) acc[mt][nt][j] = 0.f;

    const int nIter = kTot / 32;

    // prologue: stages 0..2
#pragma unroll
    for (int s = 0; s < 3; s++) {
        const uint32_t sb = uS + s * STAGE_BYTES;
        const int k0b = s * 64;
#pragma unroll
        for (int i = 0; i < 2; i++) {
            const int go = k0b + (lc + i) * 16;
            cp_async16(sb + sw[i], gA_h + go);
            cp_async16(sb + 8192 + sw[i], gB_h + go);
        }
        cp_commit();
    }

    int st = 0, ld = 3;
    for (int c = 0; c < nIter; c++) {
        if (c + 3 < nIter) {
            const uint32_t sb = uS + ld * STAGE_BYTES;
            const int k0b = (c + 3) * 64;
#pragma unroll
            for (int i = 0; i < 2; i++) {
                const int go = k0b + (lc + i) * 16;
                cp_async16(sb + sw[i], gA_h + go);
                cp_async16(sb + 8192 + sw[i], gB_h + go);
            }
            cp_commit();
            asm volatile("cp.async.wait_group 3;");
        } else {
            const int rem = nIter - 1 - c;
            if (rem == 2) cp_wait2();
            else if (rem == 1) cp_wait1();
            else cp_wait0();
        }
        __syncthreads();

        const uint32_t base = uS + st * STAGE_BYTES;
        const uint32_t uAh = base;
        const uint32_t uBh = base + 8192;

#pragma unroll
        for (int ks = 0; ks < 2; ks++) {
            const uint32_t kb = (uint32_t)ks * 32;
            uint32_t ax[2][4], bx[4][4];
#pragma unroll
            for (int mt = 0; mt < 2; mt++)
                ldm4(ax[mt], uAh + SW64(aRowOff + mt * 1024 + kb + aByte));
#pragma unroll
            for (int nt2 = 0; nt2 < 4; nt2++)
                ldm4(bx[nt2], uBh + SW64(bRowOff + nt2 * 1024 + kb + bByte));
#pragma unroll
            for (int mt = 0; mt < 2; mt++)
#pragma unroll
                for (int nt = 0; nt < 8; nt++)
                    mma_f16(acc[mt][nt], ax[mt],
                            bx[nt >> 1][(nt & 1) * 2], bx[nt >> 1][(nt & 1) * 2 + 1]);
        }
        __syncthreads();
        st = (st == NSTAGE - 1) ? 0 : st + 1;
        ld = (ld == NSTAGE - 1) ? 0 : ld + 1;
    }

    // ------------------------- epilogue -------------------------
    const int r0 = bm + wm + (lane >> 2);
    const int cb = wn + (lane & 3) * 2;

    if (mode == 1 && bn < EE) {
        float px[4], py[4], pz[4];
        int rr[4];
#pragma unroll
        for (int j = 0; j < 4; j++) {
            rr[j] = r0 + (j >> 1) * 16 + (j & 1) * 8;
            px[j] = pos[rr[j] * 3 + 0];
            py[j] = pos[rr[j] * 3 + 1];
            pz[j] = pos[rr[j] * 3 + 2];
        }
#pragma unroll
        for (int nt = 0; nt < 8; nt++) {
            const int gc = bn + cb + nt * 8;          // even global column
            const int g = gc >> 5;
            const int p = (gc & 31) >> 1;
            const float* f = freqs + ((size_t)g * PPAIR + p) * 3;
            const float fx = f[0], fy = f[1], fz = f[2];
            const float b0 = bias[gc], b1 = bias[gc + 1];
#pragma unroll
            for (int mt = 0; mt < 2; mt++) {
#pragma unroll
                for (int h = 0; h < 2; h++) {
                    const int j = mt * 2 + h;
                    const float ph = px[j] * fx + py[j] * fy + pz[j] * fz;
                    const float sn = __sinf(ph);
                    const float cs = __cosf(ph);
                    const float x1 = acc[mt][nt][h * 2 + 0] + b0;
                    const float x2 = acc[mt][nt][h * 2 + 1] + b1;
                    float2 qv, kv;
                    qv.x = x1 * cs - x2 * sn;
                    qv.y = x1 * sn + x2 * cs;
                    kv.x = cs - sn;
                    kv.y = sn + cs;
                    const size_t o = (size_t)rr[j] * EE + gc;
                    *(float2*)&outQ[o] = qv;
                    *(float2*)&outK[o] = kv;
                }
            }
        }
    } else {
        float* dst = (mode == 1) ? outV : outQ;
        const int bcol = (mode == 1) ? bn - EE : bn;
#pragma unroll
        for (int mt = 0; mt < 2; mt++) {
            const int row = r0 + mt * 16;
#pragma unroll
            for (int nt = 0; nt < 8; nt++) {
                const int col = cb + nt * 8;
                const float b0 = bias[bn + col];
                const float b1 = bias[bn + col + 1];
                float2 v0, v1;
                v0.x = acc[mt][nt][0] + b0; v0.y = acc[mt][nt][1] + b1;
                v1.x = acc[mt][nt][2] + b0; v1.y = acc[mt][nt][3] + b1;
                *(float2*)&dst[(size_t)row * EE + bcol + col]       = v0;
                *(float2*)&dst[(size_t)(row + 8) * EE + bcol + col] = v1;
            }
        }
    }
}

// ---------------------------------------------------------------------------
// Merged prep: x -> fp16; weight transpose (fp16); bias pack
// ---------------------------------------------------------------------------
#define CONV_T (NN * CCH / 4)
__global__ void prep_kernel(const float* __restrict__ x,
                            const float* __restrict__ Wq,
                            const float* __restrict__ Wv,
                            const float* __restrict__ Wo,
                            const float* __restrict__ bq,
                            const float* __restrict__ bv)
{
    int t = blockIdx.x * blockDim.x + threadIdx.x;
    if (t < CONV_T) {
        int i = t * 4;
        float4 v = *(const float4*)(x + i);
        *(__half2*)(g_xh + i)     = __floats2half2_rn(v.x, v.y);
        *(__half2*)(g_xh + i + 2) = __floats2half2_rn(v.z, v.w);
        return;
    }
    int idx = t - CONV_T;
    const int T1 = NQV * CCH;
    if (idx < T1) {
        int n = idx / CCH, k = idx % CCH;
        float f = (n < EE) ? Wq[(size_t)k * EE + n] : Wv[(size_t)k * EE + (n - EE)];
        g_wqvh[idx] = __float2half_rn(f);
    } else if (idx < T1 + CCH * EE) {
        int j = idx - T1;
        int n = j / EE, k = j % EE;
        g_woh[j] = __float2half_rn(Wo[(size_t)k * CCH + n]);
    }
    if (idx < NQV) g_bqv[idx] = (idx < EE) ? bq[idx] : bv[idx - EE];
}

// ---------------------------------------------------------------------------
// Inline segment bound (batch is sorted)
// ---------------------------------------------------------------------------
__device__ __forceinline__ int seg_lower(const int* __restrict__ batch, int t)
{
    int lo = 0, hi = NN;
    while (lo < hi) {
        int mid = (lo + hi) >> 1;
        if (batch[mid] < t) lo = mid + 1; else hi = mid;
    }
    return lo;
}

// ---------------------------------------------------------------------------
// KV segment reduction (R14/R12): emits kvT[sp][b][g][e][d] (fp32 in/out).
// ---------------------------------------------------------------------------
#define KVCH 16
__global__ __launch_bounds__(256) void kv_kernel(const int* __restrict__ batch)
{
    const int bx = blockIdx.x;
    const int gt = bx % 3;
    const int sp = bx / 3;
    const int b = blockIdx.y;
    const int s = seg_lower(batch, b);
    const int e = seg_lower(batch, b + 1);
    const int len = e - s;
    const int per = (len + KVSPLIT - 1) / KVSPLIT;
    const int rs = s + sp * per;
    const int re = min(e, rs + per);

    const int tid = threadIdx.x;
    const int gq = tid >> 6;
    const int t64 = tid & 63;
    const int d4 = ((t64 >> 3) & 7) * 4;
    const int e4 = (t64 & 7) * 4;
    const int g = gt * 4 + gq;
    const int cbase = gq * DD;

    __shared__ float sk[2][KVCH][128];
    __shared__ float sv[2][KVCH][128];

    // SWAP: stage v into sk, k into sv -> acc = v_i * k_j -> [e][d]
    const float* __restrict__ karr = g_v;
    const float* __restrict__ varr = g_k;

    float acc[4][4];
#pragma unroll
    for (int i = 0; i < 4; i++)
#pragma unroll
        for (int j = 0; j < 4; j++) acc[i][j] = 0.f;

    if (rs < re) {
        const int gcol = gt * 128;

#pragma unroll
        for (int j = 0; j < 4; j++) {
            const int i = tid + j * 256;
            const int arr = i >> 9;
            const int r = i & 511;
            const int node = r >> 5;
            const int c4 = r & 31;
            if (rs + node < re) {
                const float* src = (arr ? varr : karr)
                    + (size_t)(rs + node) * CCH + gcol + c4 * 4;
                const uint32_t dst = smem_u32(
                    arr ? &sv[0][node][c4 * 4] : &sk[0][node][c4 * 4]);
                cp_async16(dst, src);
            }
        }
        cp_commit();

        int st = 0;
        for (int n0 = rs; n0 < re; n0 += KVCH, st ^= 1) {
            const int nn = n0 + KVCH;
            if (nn < re) {
                const int nst = st ^ 1;
#pragma unroll
                for (int j = 0; j < 4; j++) {
                    const int i = tid + j * 256;
                    const int arr = i >> 9;
                    const int r = i & 511;
                    const int node = r >> 5;
                    const int c4 = r & 31;
                    if (nn + node < re) {
                        const float* src = (arr ? varr : karr)
                            + (size_t)(nn + node) * CCH + gcol + c4 * 4;
                        const uint32_t dst = smem_u32(
                            arr ? &sv[nst][node][c4 * 4] : &sk[nst][node][c4 * 4]);
                        cp_async16(dst, src);
                    }
                }
                cp_commit();
                cp_wait1();
            } else {
                cp_wait0();
            }
            __syncthreads();
            const int cnt = min(KVCH, re - n0);
            for (int c = 0; c < cnt; c++) {
                const float4 kk = *(const float4*)&sk[st][c][cbase + d4];
                const float4 vv = *(const float4*)&sv[st][c][cbase + e4];
                acc[0][0] += kk.x * vv.x; acc[0][1] += kk.x * vv.y;
                acc[0][2] += kk.x * vv.z; acc[0][3] += kk.x * vv.w;
                acc[1][0] += kk.y * vv.x; acc[1][1] += kk.y * vv.y;
                acc[1][2] += kk.y * vv.z; acc[1][3] += kk.y * vv.w;
                acc[2][0] += kk.z * vv.x; acc[2][1] += kk.z * vv.y;
                acc[2][2] += kk.z * vv.z; acc[2][3] += kk.z * vv.w;
                acc[3][0] += kk.w * vv.x; acc[3][1] += kk.w * vv.y;
                acc[3][2] += kk.w * vv.z; acc[3][3] += kk.w * vv.w;
            }
            __syncthreads();
        }
    }

    float* dst = g_kv
        + ((((size_t)sp * NGRAPH + b) * GG + g) * DD + d4) * DD + e4;
#pragma unroll
    for (int i = 0; i < 4; i++) {
        float4 o;
        o.x = acc[i][0]; o.y = acc[i][1]; o.z = acc[i][2]; o.w = acc[i][3];
        *(float4*)(dst + (size_t)i * DD) = o;
    }
}

// ---------------------------------------------------------------------------
// kv merge: g_kvm = (sum of 4 splits) / 512. 196608 float4s.
// ---------------------------------------------------------------------------
__global__ void kvmerge_kernel()
{
    const size_t tot4 = (size_t)NGRAPH * GG * DD * DD / 4;
    size_t i = (size_t)blockIdx.x * blockDim.x + threadIdx.x;
    if (i >= tot4) return;
    const float4* p = (const float4*)g_kv;
    const float4 a = p[i];
    const float4 b = p[i + tot4];
    const float4 c = p[i + 2 * tot4];
    const float4 d = p[i + 3 * tot4];
    const float inv = 1.0f / 512.0f;
    float4 o;
    o.x = (a.x + b.x + c.x + d.x) * inv;
    o.y = (a.y + b.y + c.y + d.y) * inv;
    o.z = (a.z + b.z + c.z + d.z) * inv;
    o.w = (a.w + b.w + c.w + d.w) * inv;
    ((float4*)g_kvm)[i] = o;
}

// ---------------------------------------------------------------------------
// Apply: warp-per-group, merged kv column in registers; fp32 math, fp16 out.
// ASPLIT=4 (256 blocks), AQN=16, 2-node x 4-partial-sum inner loop.
// ---------------------------------------------------------------------------
#define AQN 16
#define ASPLIT 4
__global__ __launch_bounds__(384) void attn_kernel(const int* __restrict__ batch)
{
    const int c = blockIdx.x;
    const int b = blockIdx.y;
    const int s = seg_lower(batch, b);
    const int e = seg_lower(batch, b + 1);
    const int len = e - s;
    const int per = (len + ASPLIT - 1) / ASPLIT;
    const int rs = s + c * per;
    const int re = min(e, rs + per);
    if (rs >= re) return;

    const int tid = threadIdx.x;
    const int g = tid >> 5;
    const int lane = tid & 31;

    // merged kv column -> 32 registers
    float kvc[DD];
    {
        const float* p0 = g_kvm + (((size_t)b * GG + g) * DD + lane) * DD;
#pragma unroll
        for (int d = 0; d < DD; d += 4)
            *(float4*)&kvc[d] = *(const float4*)(p0 + d);
    }

    __shared__ float qs[2][AQN][CCH];   // 2 x 24 KB

    // loader: AQN*96 = 1536 float4 per stage -> 4 per thread
#pragma unroll
    for (int k = 0; k < 4; k++) {
        const int idx = tid + k * 384;
        const int node = idx / 96;
        const int c4 = idx % 96;
        if (rs + node < re)
            cp_async16(smem_u32(&qs[0][node][c4 * 4]),
                       g_q + (size_t)(rs + node) * EE + c4 * 4);
    }
    cp_commit();

    int st = 0;
    for (int n0 = rs; n0 < re; n0 += AQN, st ^= 1) {
        const int nn = n0 + AQN;
        if (nn < re) {
            const int nst = st ^ 1;
#pragma unroll
            for (int k = 0; k < 4; k++) {
                const int idx = tid + k * 384;
                const int node = idx / 96;
                const int c4 = idx % 96;
                if (nn + node < re)
                    cp_async16(smem_u32(&qs[nst][node][c4 * 4]),
                               g_q + (size_t)(nn + node) * EE + c4 * 4);
            }
            cp_commit();
            cp_wait1();
        } else {
            cp_wait0();
        }
        __syncthreads();

        const int cnt = min(AQN, re - n0);
        for (int i = 0; i < cnt; i += 2) {
            const bool two = (i + 1 < cnt);
            const float* q0 = &qs[st][i][g * DD];
            const float* q1 = &qs[st][two ? i + 1 : i][g * DD];
            float a0 = 0.f, a1 = 0.f, a2 = 0.f, a3 = 0.f;
            float b0 = 0.f, b1 = 0.f, b2 = 0.f, b3 = 0.f;
#pragma unroll
            for (int d = 0; d < DD; d += 4) {
                const float4 x0 = *(const float4*)(q0 + d);
                const float4 x1 = *(const float4*)(q1 + d);
                a0 += x0.x * kvc[d + 0];
                a1 += x0.y * kvc[d + 1];
                a2 += x0.z * kvc[d + 2];
                a3 += x0.w * kvc[d + 3];
                b0 += x1.x * kvc[d + 0];
                b1 += x1.y * kvc[d + 1];
                b2 += x1.z * kvc[d + 2];
                b3 += x1.w * kvc[d + 3];
            }
            g_ah[(size_t)(n0 + i) * EE + g * DD + lane] =
                __float2half_rn((a0 + a1) + (a2 + a3));
            if (two)
                g_ah[(size_t)(n0 + i + 1) * EE + g * DD + lane] =
                    __float2half_rn((b0 + b1) + (b2 + b3));
        }
        __syncthreads();
    }
}

// ---------------------------------------------------------------------------
// Launch
// ---------------------------------------------------------------------------
extern "C" void kernel_launch(void* const* d_in, const int* in_sizes, int n_in,
                              void* d_out, int out_size)
{
    const float* x     = (const float*)d_in[0];
    const float* pos   = (const float*)d_in[1];
    const int*   batch = (const int*)d_in[2];
    const float* Wq    = (const float*)d_in[3];
    const float* bq    = (const float*)d_in[4];
    const float* Wv    = (const float*)d_in[5];
    const float* bv    = (const float*)d_in[6];
    const float* Wo    = (const float*)d_in[7];
    const float* bo    = (const float*)d_in[8];
    const float* freqs = (const float*)d_in[9];
    float* out = (float*)d_out;

    float *gq, *gv, *gk, *gbqv;
    __half *gxh, *gah, *gwqvh, *gwoh;
    cudaGetSymbolAddress((void**)&gq, g_q);
    cudaGetSymbolAddress((void**)&gv, g_v);
    cudaGetSymbolAddress((void**)&gk, g_k);
    cudaGetSymbolAddress((void**)&gbqv, g_bqv);
    cudaGetSymbolAddress((void**)&gxh, g_xh);
    cudaGetSymbolAddress((void**)&gah, g_ah);
    cudaGetSymbolAddress((void**)&gwqvh, g_wqvh);
    cudaGetSymbolAddress((void**)&gwoh, g_woh);

    cudaFuncSetAttribute(gemm_mma,
                         cudaFuncAttributeMaxDynamicSharedMemorySize, GEMM_SMEM);

    // 1) merged prep: x -> fp16, weight transpose, bias pack
    const int prepT = CONV_T + NQV * CCH + CCH * EE;
    prep_kernel<<<(prepT + 255) / 256, 256>>>(x, Wq, Wv, Wo, bq, bv);

    // 2) fused QV projection + RoPE epilogue -> g_q, g_k, g_v (fp32)
    gemm_mma<<<dim3(NQV / 128, NN / 128), 256, GEMM_SMEM>>>(
        gxh, gwqvh, gbqv, gq, gv, gk, pos, freqs, CCH, 1);

    // 3) kvT = segsum(v outer k) per node-split -> [sp][b][g][e][d]
    kv_kernel<<<dim3(3 * KVSPLIT, NGRAPH), 256>>>(batch);

    // 3b) merge the 4 splits (scaled by 1/512)
    kvmerge_kernel<<<(NGRAPH * GG * DD * DD / 4 + 255) / 256, 256>>>();

    // 4) attn = q . kvm[batch] -> fp16
    attn_kernel<<<dim3(ASPLIT, NGRAPH), 384>>>(batch);

    // 5) out = attn @ Wo + bo
    gemm_mma<<<dim3(EE / 128, NN / 128), 256, GEMM_SMEM>>>(
        gah, gwoh, bo, out, out, nullptr, nullptr, nullptr, EE, 0);
}